// round 11
// baseline (speedup 1.0000x reference)
#include <cuda_runtime.h>
#include <math.h>

#define B 256
#define T 2048
#define V 64
#define H 64
#define EOS 2

// Precomputed tables
__device__ float g_gtable[V * 4];
__device__ float g_quad[14 * V];   // [slot s][col v], trace-folded quadratic head

__device__ __forceinline__ float gelu_exact(float x) {
    return 0.5f * x * (1.0f + erff(x * 0.70710678118654752440f));
}

// quaternion as float4: (w,x,y,z) = (q.x,q.y,q.z,q.w)
__device__ __forceinline__ float4 qmul(float4 a, float4 b) {
    float4 r;
    r.x = a.x * b.x - a.y * b.y - a.z * b.z - a.w * b.w;
    r.y = a.x * b.y + a.y * b.x + a.z * b.w - a.w * b.z;
    r.z = a.x * b.z - a.y * b.w + a.z * b.x + a.w * b.y;
    r.w = a.x * b.w + a.y * b.z - a.z * b.y + a.w * b.x;
    return r;
}
__device__ __forceinline__ float4 qnorm(float4 q) {
    float n2 = q.x * q.x + q.y * q.y + q.z * q.z + q.w * q.w;
    float inv = rsqrtf(fmaxf(n2, 1e-24f));
    q.x *= inv; q.y *= inv; q.z *= inv; q.w *= inv;
    return q;
}
__device__ __forceinline__ float4 shfl_up4(float4 v, int delta) {
    float4 r;
    r.x = __shfl_up_sync(0xFFFFFFFFu, v.x, delta);
    r.y = __shfl_up_sync(0xFFFFFFFFu, v.y, delta);
    r.z = __shfl_up_sync(0xFFFFFFFFu, v.z, delta);
    r.w = __shfl_up_sync(0xFFFFFFFFu, v.w, delta);
    return r;
}
__device__ __forceinline__ float wred(float p) {
    #pragma unroll
    for (int off = 16; off > 0; off >>= 1) p += __shfl_down_sync(0xFFFFFFFFu, p, off);
    return p;
}
__device__ __forceinline__ void stcs4(float* p, float4 v) {
    asm volatile("st.global.cs.v4.f32 [%0], {%1,%2,%3,%4};"
                 :: "l"(p), "f"(v.x), "f"(v.y), "f"(v.z), "f"(v.w) : "memory");
}
// acos via A&S 4.4.45: acos(u) = sqrt(1-u) * P(u), u in [0,1], |err| <= 2e-8
__device__ __forceinline__ float acos_poly(float u) {
    float p = fmaf(u, -0.0012624911f, 0.0066700901f);
    p = fmaf(u, p, -0.0170881256f);
    p = fmaf(u, p,  0.0308918810f);
    p = fmaf(u, p, -0.0501743046f);
    p = fmaf(u, p,  0.0889789874f);
    p = fmaf(u, p, -0.2145988016f);
    p = fmaf(u, p,  1.5707963050f);
    return sqrtf(1.0f - u) * p;
}

// ---------------------------------------------------------------------------
// Kernel 1 (precompute), 128 blocks x 64 threads.  (R4-proven, unchanged)
// ---------------------------------------------------------------------------
__global__ void precompute_kernel(const float* __restrict__ eW1,
                                  const float* __restrict__ eb1,
                                  const float* __restrict__ eW2,
                                  const float* __restrict__ eb2,
                                  const float* __restrict__ hW1,
                                  const float* __restrict__ hb1,
                                  const float* __restrict__ hW2,
                                  const float* __restrict__ hb2) {
    int blk = blockIdx.x;
    int j = threadIdx.x;          // 0..63
    int lane = j & 31, w = j >> 5;

    if (blk < 64) {
        int v = blk;
        float x = eW1[v * H + j] + eb1[j];
        float h = gelu_exact(x);
        float p0 = wred(h * eW2[j * 4 + 0]);
        float p1 = wred(h * eW2[j * 4 + 1]);
        float p2 = wred(h * eW2[j * 4 + 2]);
        float p3 = wred(h * eW2[j * 4 + 3]);
        __shared__ float red[2][4];
        if (lane == 0) { red[w][0] = p0; red[w][1] = p1; red[w][2] = p2; red[w][3] = p3; }
        __syncthreads();
        if (j == 0) {
            float a0 = red[0][0] + red[1][0] + eb2[0];
            float a1 = red[0][1] + red[1][1] + eb2[1];
            float a2 = red[0][2] + red[1][2] + eb2[2];
            float a3 = red[0][3] + red[1][3] + eb2[3];
            float n = sqrtf(a0 * a0 + a1 * a1 + a2 * a2 + a3 * a3);
            float inv = 1.0f / fmaxf(n, 1e-12f);
            float4 g = make_float4(a0 * inv, a1 * inv, a2 * inv, a3 * inv);
            if (v == EOS) g = make_float4(1.0f, 0.0f, 0.0f, 0.0f);
            reinterpret_cast<float4*>(g_gtable)[v] = g;
        }
    } else {
        int v = blk - 64;
        float b  = hb1[j];
        float wv = hW2[j * V + v];
        float w0 = hW1[0 * H + j], w1 = hW1[1 * H + j];
        float w2 = hW1[2 * H + j], w3 = hW1[3 * H + j];
        float sig2 = 0.25f * (w0 * w0 + w1 * w1 + w2 * w2 + w3 * w3);
        float phi = 0.3989422804014327f * expf(-0.5f * b * b);
        float cdf = 0.5f * (1.0f + erff(b * 0.70710678118654752f));
        float g0 = b * cdf;
        float g1 = cdf + b * phi;
        float g2 = 0.5f * (2.0f - b * b) * phi;
        float g3 = -b * (4.0f - b * b) * phi * (1.0f / 6.0f);
        float b2 = b * b;
        float g4 = (-4.0f + 7.0f * b2 - b2 * b2) * phi * (1.0f / 24.0f);
        float e1 = g1 + 3.0f * sig2 * g3;
        float e2 = g2 + 3.0f * sig2 * g4;

        float c[15];
        c[0] = wv * g0;
        float l = wv * e1;
        c[1] = l * w0; c[2] = l * w1; c[3] = l * w2; c[4] = l * w3;
        float q = wv * e2;
        c[5]  = q * w0 * w0;        c[6]  = 2.0f * q * w0 * w1;
        c[7]  = 2.0f * q * w0 * w2; c[8]  = 2.0f * q * w0 * w3;
        c[9]  = q * w1 * w1;        c[10] = 2.0f * q * w1 * w2;
        c[11] = 2.0f * q * w1 * w3; c[12] = q * w2 * w2;
        c[13] = 2.0f * q * w2 * w3; c[14] = q * w3 * w3;

        __shared__ float redq[2][15];
        float tot[15];
        #pragma unroll
        for (int s = 0; s < 15; s++) {
            float r = wred(c[s]);
            if (lane == 0) redq[w][s] = r;
        }
        __syncthreads();
        if (j == 0) {
            #pragma unroll
            for (int s = 0; s < 15; s++) tot[s] = redq[0][s] + redq[1][s];
            tot[0] += hb2[v];
            // fold z^2 slot: c3^2 = 1 - c0^2 - c1^2 - c2^2 (|C| = 1 exactly)
            tot[0]  += tot[14];
            tot[5]  -= tot[14];
            tot[9]  -= tot[14];
            tot[12] -= tot[14];
            #pragma unroll
            for (int s = 0; s < 14; s++) g_quad[s * V + v] = tot[s];
        }
    }
}

// ---------------------------------------------------------------------------
// Kernel 2 (fused): scan + head, one block per batch row.
// Head uses per-row precomputed monomial vectors (mbuf, 4 chunks of 512 rows)
// so each lane does 52 FFMA and NO FMULs. Dynamic SMEM (~75 KB).
// ---------------------------------------------------------------------------
extern __shared__ __align__(16) char dynsmem[];

__global__ __launch_bounds__(256, 2) void fused_kernel(const int* __restrict__ tokens,
                                                       float* __restrict__ logits,
                                                       float* __restrict__ sigmas) {
    // carve dynamic smem
    float4* Cbuf = reinterpret_cast<float4*>(dynsmem);                 // 32 KB, [i*256+t]
    float4* mbuf = reinterpret_cast<float4*>(dynsmem + 32768);         // 32 KB, 512 rows x 4 vec
    float*  sbuf = reinterpret_cast<float*>(dynsmem + 65536);          // 8 KB
    float4* gt   = reinterpret_cast<float4*>(dynsmem + 73728);         // 1 KB
    float4* warp_tot = reinterpret_cast<float4*>(dynsmem + 74752);     // 128 B

    int b = blockIdx.x;
    int t = threadIdx.x;
    int lane = t & 31;
    int w = t >> 5;

    if (t < V) gt[t] = reinterpret_cast<const float4*>(g_gtable)[t];
    __syncthreads();

    // ---- Phase A: scan (8 tokens per thread), R8-proven ----
    const int4* tp = reinterpret_cast<const int4*>(tokens + b * T + t * 8);
    int4 ta = tp[0];
    int4 tb = tp[1];
    int tok[8] = {ta.x, ta.y, ta.z, ta.w, tb.x, tb.y, tb.z, tb.w};

    float4 P = gt[tok[0]];
    #pragma unroll
    for (int i = 1; i < 8; i++) P = qmul(P, gt[tok[i]]);

    #pragma unroll
    for (int off = 1; off < 32; off <<= 1) {
        float4 o = shfl_up4(P, off);
        if (lane >= off) P = qmul(o, P);
    }

    if (lane == 31) warp_tot[w] = P;
    float4 laneExcl = shfl_up4(P, 1);
    __syncthreads();

    float4 E = make_float4(1.0f, 0.0f, 0.0f, 0.0f);
    for (int i = 0; i < w; i++) E = qmul(E, warp_tot[i]);
    if (lane > 0) E = qmul(E, laneExcl);
    E = qnorm(E);

    float4 C = E;
    #pragma unroll
    for (int i = 0; i < 8; i++) {
        C = qnorm(qmul(C, gt[tok[i]]));
        Cbuf[i * 256 + t] = C;                 // 16B thread stride: conflict-free
        sbuf[t * 8 + i] = acos_poly(fminf(fabsf(C.x), 1.0f - 1e-7f));
    }
    __syncthreads();

    // ---- Phase B: per-chunk monomial gen + head ----
    int col = lane & 15;
    int half = lane >> 4;

    float4 cf[14];
    const float4* gq = reinterpret_cast<const float4*>(g_quad);
    #pragma unroll
    for (int s = 0; s < 14; s++) cf[s] = gq[s * 16 + col];

    int base = w * 2 + half;                   // 0..15
    float* outBase = logits + (long)b * T * V + (long)base * V + col * 4;

    #pragma unroll 1
    for (int c = 0; c < 4; c++) {
        // gen: 2 rows per thread (512 rows per chunk)
        #pragma unroll
        for (int m = 0; m < 2; m++) {
            int rl = m * 256 + t;              // row within chunk
            int r = c * 512 + rl;              // row within block
            float4 Cr = Cbuf[(r & 7) * 256 + (r >> 3)];
            float4* mb = mbuf + rl * 4;
            mb[(0 + rl) & 3] = Cr;
            mb[(1 + rl) & 3] = make_float4(Cr.x * Cr.x, Cr.x * Cr.y, Cr.x * Cr.z, Cr.x * Cr.w);
            mb[(2 + rl) & 3] = make_float4(Cr.y * Cr.y, Cr.y * Cr.z, Cr.y * Cr.w, Cr.z * Cr.z);
            mb[(3 + rl) & 3] = make_float4(Cr.z * Cr.w, 0.0f, 0.0f, 0.0f);
        }
        __syncthreads();

        // head: 32 iterations x 16 rows
        #pragma unroll 4
        for (int i = 0; i < 32; i++) {
            int rl = i * 16 + base;
            const float4* mb = mbuf + rl * 4;
            float4 M0 = mb[(0 + rl) & 3];      // Cx Cy Cz Cw
            float4 M1 = mb[(1 + rl) & 3];      // xx xy xz xw
            float4 M2 = mb[(2 + rl) & 3];      // yy yz yw zz
            float  mZW = mb[(3 + rl) & 3].x;   // zw

            float4 a = cf[0];
            a.x = fmaf(M0.x, cf[1].x, a.x);  a.y = fmaf(M0.x, cf[1].y, a.y);
            a.z = fmaf(M0.x, cf[1].z, a.z);  a.w = fmaf(M0.x, cf[1].w, a.w);
            a.x = fmaf(M0.y, cf[2].x, a.x);  a.y = fmaf(M0.y, cf[2].y, a.y);
            a.z = fmaf(M0.y, cf[2].z, a.z);  a.w = fmaf(M0.y, cf[2].w, a.w);
            a.x = fmaf(M0.z, cf[3].x, a.x);  a.y = fmaf(M0.z, cf[3].y, a.y);
            a.z = fmaf(M0.z, cf[3].z, a.z);  a.w = fmaf(M0.z, cf[3].w, a.w);
            a.x = fmaf(M0.w, cf[4].x, a.x);  a.y = fmaf(M0.w, cf[4].y, a.y);
            a.z = fmaf(M0.w, cf[4].z, a.z);  a.w = fmaf(M0.w, cf[4].w, a.w);
            a.x = fmaf(M1.x, cf[5].x, a.x);  a.y = fmaf(M1.x, cf[5].y, a.y);
            a.z = fmaf(M1.x, cf[5].z, a.z);  a.w = fmaf(M1.x, cf[5].w, a.w);
            a.x = fmaf(M1.y, cf[6].x, a.x);  a.y = fmaf(M1.y, cf[6].y, a.y);
            a.z = fmaf(M1.y, cf[6].z, a.z);  a.w = fmaf(M1.y, cf[6].w, a.w);
            a.x = fmaf(M1.z, cf[7].x, a.x);  a.y = fmaf(M1.z, cf[7].y, a.y);
            a.z = fmaf(M1.z, cf[7].z, a.z);  a.w = fmaf(M1.z, cf[7].w, a.w);
            a.x = fmaf(M1.w, cf[8].x, a.x);  a.y = fmaf(M1.w, cf[8].y, a.y);
            a.z = fmaf(M1.w, cf[8].z, a.z);  a.w = fmaf(M1.w, cf[8].w, a.w);
            a.x = fmaf(M2.x, cf[9].x, a.x);  a.y = fmaf(M2.x, cf[9].y, a.y);
            a.z = fmaf(M2.x, cf[9].z, a.z);  a.w = fmaf(M2.x, cf[9].w, a.w);
            a.x = fmaf(M2.y, cf[10].x, a.x); a.y = fmaf(M2.y, cf[10].y, a.y);
            a.z = fmaf(M2.y, cf[10].z, a.z); a.w = fmaf(M2.y, cf[10].w, a.w);
            a.x = fmaf(M2.z, cf[11].x, a.x); a.y = fmaf(M2.z, cf[11].y, a.y);
            a.z = fmaf(M2.z, cf[11].z, a.z); a.w = fmaf(M2.z, cf[11].w, a.w);
            a.x = fmaf(M2.w, cf[12].x, a.x); a.y = fmaf(M2.w, cf[12].y, a.y);
            a.z = fmaf(M2.w, cf[12].z, a.z); a.w = fmaf(M2.w, cf[12].w, a.w);
            a.x = fmaf(mZW,  cf[13].x, a.x); a.y = fmaf(mZW,  cf[13].y, a.y);
            a.z = fmaf(mZW,  cf[13].z, a.z); a.w = fmaf(mZW,  cf[13].w, a.w);

            stcs4(outBase + (long)(c * 512 + i * 16) * V, a);
        }
        __syncthreads();
    }

    // ---- sigmas: coalesced copy-out from SMEM ----
    const float4* sb4 = reinterpret_cast<const float4*>(sbuf);
    float* so = sigmas + (long)b * T;
    stcs4(so + t * 4, sb4[t]);
    stcs4(so + 1024 + t * 4, sb4[t + 256]);
}

#define FUSED_SMEM (32768 + 32768 + 8192 + 1024 + 128)

// ---------------------------------------------------------------------------
extern "C" void kernel_launch(void* const* d_in, const int* in_sizes, int n_in,
                              void* d_out, int out_size) {
    const int*   tokens = (const int*)  d_in[0];
    const float* eW1    = (const float*)d_in[1];
    const float* eb1    = (const float*)d_in[2];
    const float* eW2    = (const float*)d_in[3];
    const float* eb2    = (const float*)d_in[4];
    const float* hW1    = (const float*)d_in[5];
    const float* hb1    = (const float*)d_in[6];
    const float* hW2    = (const float*)d_in[7];
    const float* hb2    = (const float*)d_in[8];

    float* out    = (float*)d_out;
    float* logits = out;                       // (B,T,V)
    float* sigmas = out + (long)B * T * V;     // (B,T)

    cudaFuncSetAttribute(fused_kernel,
                         cudaFuncAttributeMaxDynamicSharedMemorySize, FUSED_SMEM);

    precompute_kernel<<<128, 64>>>(eW1, eb1, eW2, eb2, hW1, hb1, hW2, hb2);
    fused_kernel<<<B, 256, FUSED_SMEM>>>(tokens, logits, sigmas);
}

// round 12
// speedup vs baseline: 1.2695x; 1.2695x over previous
#include <cuda_runtime.h>
#include <math.h>

#define B 256
#define T 2048
#define V 64
#define H 64
#define EOS 2

// Precomputed tables
__device__ float g_gtable[V * 4];
__device__ float g_quad[14 * V];   // [slot s][col v], trace-folded quadratic head

__device__ __forceinline__ float gelu_exact(float x) {
    return 0.5f * x * (1.0f + erff(x * 0.70710678118654752440f));
}

// quaternion as float4: (w,x,y,z) = (q.x,q.y,q.z,q.w)
__device__ __forceinline__ float4 qmul(float4 a, float4 b) {
    float4 r;
    r.x = a.x * b.x - a.y * b.y - a.z * b.z - a.w * b.w;
    r.y = a.x * b.y + a.y * b.x + a.z * b.w - a.w * b.z;
    r.z = a.x * b.z - a.y * b.w + a.z * b.x + a.w * b.y;
    r.w = a.x * b.w + a.y * b.z - a.z * b.y + a.w * b.x;
    return r;
}
__device__ __forceinline__ float4 qnorm(float4 q) {
    float n2 = q.x * q.x + q.y * q.y + q.z * q.z + q.w * q.w;
    float inv = rsqrtf(fmaxf(n2, 1e-24f));
    q.x *= inv; q.y *= inv; q.z *= inv; q.w *= inv;
    return q;
}
__device__ __forceinline__ float4 shfl_up4(float4 v, int delta) {
    float4 r;
    r.x = __shfl_up_sync(0xFFFFFFFFu, v.x, delta);
    r.y = __shfl_up_sync(0xFFFFFFFFu, v.y, delta);
    r.z = __shfl_up_sync(0xFFFFFFFFu, v.z, delta);
    r.w = __shfl_up_sync(0xFFFFFFFFu, v.w, delta);
    return r;
}
__device__ __forceinline__ float wred(float p) {
    #pragma unroll
    for (int off = 16; off > 0; off >>= 1) p += __shfl_down_sync(0xFFFFFFFFu, p, off);
    return p;
}
__device__ __forceinline__ void stcs4(float* p, float4 v) {
    asm volatile("st.global.cs.v4.f32 [%0], {%1,%2,%3,%4};"
                 :: "l"(p), "f"(v.x), "f"(v.y), "f"(v.z), "f"(v.w) : "memory");
}
// acos via A&S 4.4.45: acos(u) = sqrt(1-u) * P(u), u in [0,1], |err| <= 2e-8
__device__ __forceinline__ float acos_poly(float u) {
    float p = fmaf(u, -0.0012624911f, 0.0066700901f);
    p = fmaf(u, p, -0.0170881256f);
    p = fmaf(u, p,  0.0308918810f);
    p = fmaf(u, p, -0.0501743046f);
    p = fmaf(u, p,  0.0889789874f);
    p = fmaf(u, p, -0.2145988016f);
    p = fmaf(u, p,  1.5707963050f);
    return sqrtf(1.0f - u) * p;
}
__device__ __forceinline__ float sig_from_w(float wv) {
    return acos_poly(fminf(fabsf(wv), 1.0f - 1e-7f));
}

// ---------------------------------------------------------------------------
// Kernel 1 (precompute), 128 blocks x 64 threads.  (R4-proven, unchanged)
// ---------------------------------------------------------------------------
__global__ void precompute_kernel(const float* __restrict__ eW1,
                                  const float* __restrict__ eb1,
                                  const float* __restrict__ eW2,
                                  const float* __restrict__ eb2,
                                  const float* __restrict__ hW1,
                                  const float* __restrict__ hb1,
                                  const float* __restrict__ hW2,
                                  const float* __restrict__ hb2) {
    int blk = blockIdx.x;
    int j = threadIdx.x;          // 0..63
    int lane = j & 31, w = j >> 5;

    if (blk < 64) {
        int v = blk;
        float x = eW1[v * H + j] + eb1[j];
        float h = gelu_exact(x);
        float p0 = wred(h * eW2[j * 4 + 0]);
        float p1 = wred(h * eW2[j * 4 + 1]);
        float p2 = wred(h * eW2[j * 4 + 2]);
        float p3 = wred(h * eW2[j * 4 + 3]);
        __shared__ float red[2][4];
        if (lane == 0) { red[w][0] = p0; red[w][1] = p1; red[w][2] = p2; red[w][3] = p3; }
        __syncthreads();
        if (j == 0) {
            float a0 = red[0][0] + red[1][0] + eb2[0];
            float a1 = red[0][1] + red[1][1] + eb2[1];
            float a2 = red[0][2] + red[1][2] + eb2[2];
            float a3 = red[0][3] + red[1][3] + eb2[3];
            float n = sqrtf(a0 * a0 + a1 * a1 + a2 * a2 + a3 * a3);
            float inv = 1.0f / fmaxf(n, 1e-12f);
            float4 g = make_float4(a0 * inv, a1 * inv, a2 * inv, a3 * inv);
            if (v == EOS) g = make_float4(1.0f, 0.0f, 0.0f, 0.0f);
            reinterpret_cast<float4*>(g_gtable)[v] = g;
        }
    } else {
        int v = blk - 64;
        float b  = hb1[j];
        float wv = hW2[j * V + v];
        float w0 = hW1[0 * H + j], w1 = hW1[1 * H + j];
        float w2 = hW1[2 * H + j], w3 = hW1[3 * H + j];
        float sig2 = 0.25f * (w0 * w0 + w1 * w1 + w2 * w2 + w3 * w3);
        float phi = 0.3989422804014327f * expf(-0.5f * b * b);
        float cdf = 0.5f * (1.0f + erff(b * 0.70710678118654752f));
        float g0 = b * cdf;
        float g1 = cdf + b * phi;
        float g2 = 0.5f * (2.0f - b * b) * phi;
        float g3 = -b * (4.0f - b * b) * phi * (1.0f / 6.0f);
        float b2 = b * b;
        float g4 = (-4.0f + 7.0f * b2 - b2 * b2) * phi * (1.0f / 24.0f);
        float e1 = g1 + 3.0f * sig2 * g3;
        float e2 = g2 + 3.0f * sig2 * g4;

        float c[15];
        c[0] = wv * g0;
        float l = wv * e1;
        c[1] = l * w0; c[2] = l * w1; c[3] = l * w2; c[4] = l * w3;
        float q = wv * e2;
        c[5]  = q * w0 * w0;        c[6]  = 2.0f * q * w0 * w1;
        c[7]  = 2.0f * q * w0 * w2; c[8]  = 2.0f * q * w0 * w3;
        c[9]  = q * w1 * w1;        c[10] = 2.0f * q * w1 * w2;
        c[11] = 2.0f * q * w1 * w3; c[12] = q * w2 * w2;
        c[13] = 2.0f * q * w2 * w3; c[14] = q * w3 * w3;

        __shared__ float redq[2][15];
        float tot[15];
        #pragma unroll
        for (int s = 0; s < 15; s++) {
            float r = wred(c[s]);
            if (lane == 0) redq[w][s] = r;
        }
        __syncthreads();
        if (j == 0) {
            #pragma unroll
            for (int s = 0; s < 15; s++) tot[s] = redq[0][s] + redq[1][s];
            tot[0] += hb2[v];
            // fold z^2 slot: c3^2 = 1 - c0^2 - c1^2 - c2^2 (|C| = 1 exactly)
            tot[0]  += tot[14];
            tot[5]  -= tot[14];
            tot[9]  -= tot[14];
            tot[12] -= tot[14];
            #pragma unroll
            for (int s = 0; s < 14; s++) g_quad[s * V + v] = tot[s];
        }
    }
}

// ---------------------------------------------------------------------------
// Kernel 2 (fused): scan + head, one block per batch row. (R8-proven config:
// launch_bounds(256,2), transposed Cbuf, streaming stores.)  acos moved out
// of the scan critical path into the copy-out tail.
// ---------------------------------------------------------------------------
__global__ __launch_bounds__(256, 2) void fused_kernel(const int* __restrict__ tokens,
                                                       float* __restrict__ logits,
                                                       float* __restrict__ sigmas) {
    __shared__ float4 gt[V];
    __shared__ float4 warp_tot[8];
    __shared__ __align__(16) float4 Cbuf[T];   // [i][t] = i*256 + t
    __shared__ __align__(16) float  sbuf[T];   // raw C.x (w components)

    int b = blockIdx.x;
    int t = threadIdx.x;
    int lane = t & 31;
    int w = t >> 5;

    if (t < V) gt[t] = reinterpret_cast<const float4*>(g_gtable)[t];
    __syncthreads();

    // ---- Phase A: scan (8 tokens per thread) ----
    const int4* tp = reinterpret_cast<const int4*>(tokens + b * T + t * 8);
    int4 ta = tp[0];
    int4 tb = tp[1];
    int tok[8] = {ta.x, ta.y, ta.z, ta.w, tb.x, tb.y, tb.z, tb.w};

    // local product (no intermediate norms: unit inputs, drift ~1e-7)
    float4 P = gt[tok[0]];
    #pragma unroll
    for (int i = 1; i < 8; i++) P = qmul(P, gt[tok[i]]);

    // warp Kogge-Stone scan, norm-free
    #pragma unroll
    for (int off = 1; off < 32; off <<= 1) {
        float4 o = shfl_up4(P, off);
        if (lane >= off) P = qmul(o, P);
    }

    if (lane == 31) warp_tot[w] = P;
    float4 laneExcl = shfl_up4(P, 1);
    __syncthreads();

    float4 E = make_float4(1.0f, 0.0f, 0.0f, 0.0f);
    for (int i = 0; i < w; i++) E = qmul(E, warp_tot[i]);
    if (lane > 0) E = qmul(E, laneExcl);
    E = qnorm(E);

    // per-step recompute with per-step normalization (matches reference)
    float4 C = E;
    #pragma unroll
    for (int i = 0; i < 8; i++) {
        C = qnorm(qmul(C, gt[tok[i]]));
        Cbuf[i * 256 + t] = C;                 // 16B thread stride: conflict-free
        sbuf[t * 8 + i] = C.x;                 // raw w; acos deferred to tail
    }
    __syncthreads();

    // ---- Phase B: head. half-warp -> one 256B logits row (coalesced) ----
    int col = lane & 15;
    int half = lane >> 4;

    float4 cf[14];
    const float4* gq = reinterpret_cast<const float4*>(g_quad);
    #pragma unroll
    for (int s = 0; s < 14; s++) cf[s] = gq[s * 16 + col];

    // row = i*16 + w*2 + half; Cbuf index = (row&7)*256 + (row>>3)
    int rlow = (w * 2 + half) & 7;
    int rhigh = (w * 2 + half) >> 3;
    const float4* cbase = Cbuf + rlow * 256 + rhigh;
    float* outp = logits + (long)b * T * V + (long)(w * 2 + half) * V + col * 4;

    #pragma unroll 4
    for (int i = 0; i < 128; i++) {
        float4 Cr = cbase[i * 2];              // broadcast LDS.128

        float m4  = Cr.x * Cr.x, m5  = Cr.x * Cr.y, m6  = Cr.x * Cr.z, m7 = Cr.x * Cr.w;
        float m8  = Cr.y * Cr.y, m9  = Cr.y * Cr.z, m10 = Cr.y * Cr.w;
        float m11 = Cr.z * Cr.z, m12 = Cr.z * Cr.w;

        float4 a = cf[0];
        a.x = fmaf(Cr.x, cf[1].x, a.x);  a.y = fmaf(Cr.x, cf[1].y, a.y);
        a.z = fmaf(Cr.x, cf[1].z, a.z);  a.w = fmaf(Cr.x, cf[1].w, a.w);
        a.x = fmaf(Cr.y, cf[2].x, a.x);  a.y = fmaf(Cr.y, cf[2].y, a.y);
        a.z = fmaf(Cr.y, cf[2].z, a.z);  a.w = fmaf(Cr.y, cf[2].w, a.w);
        a.x = fmaf(Cr.z, cf[3].x, a.x);  a.y = fmaf(Cr.z, cf[3].y, a.y);
        a.z = fmaf(Cr.z, cf[3].z, a.z);  a.w = fmaf(Cr.z, cf[3].w, a.w);
        a.x = fmaf(Cr.w, cf[4].x, a.x);  a.y = fmaf(Cr.w, cf[4].y, a.y);
        a.z = fmaf(Cr.w, cf[4].z, a.z);  a.w = fmaf(Cr.w, cf[4].w, a.w);
        a.x = fmaf(m4,  cf[5].x, a.x);   a.y = fmaf(m4,  cf[5].y, a.y);
        a.z = fmaf(m4,  cf[5].z, a.z);   a.w = fmaf(m4,  cf[5].w, a.w);
        a.x = fmaf(m5,  cf[6].x, a.x);   a.y = fmaf(m5,  cf[6].y, a.y);
        a.z = fmaf(m5,  cf[6].z, a.z);   a.w = fmaf(m5,  cf[6].w, a.w);
        a.x = fmaf(m6,  cf[7].x, a.x);   a.y = fmaf(m6,  cf[7].y, a.y);
        a.z = fmaf(m6,  cf[7].z, a.z);   a.w = fmaf(m6,  cf[7].w, a.w);
        a.x = fmaf(m7,  cf[8].x, a.x);   a.y = fmaf(m7,  cf[8].y, a.y);
        a.z = fmaf(m7,  cf[8].z, a.z);   a.w = fmaf(m7,  cf[8].w, a.w);
        a.x = fmaf(m8,  cf[9].x, a.x);   a.y = fmaf(m8,  cf[9].y, a.y);
        a.z = fmaf(m8,  cf[9].z, a.z);   a.w = fmaf(m8,  cf[9].w, a.w);
        a.x = fmaf(m9,  cf[10].x, a.x);  a.y = fmaf(m9,  cf[10].y, a.y);
        a.z = fmaf(m9,  cf[10].z, a.z);  a.w = fmaf(m9,  cf[10].w, a.w);
        a.x = fmaf(m10, cf[11].x, a.x);  a.y = fmaf(m10, cf[11].y, a.y);
        a.z = fmaf(m10, cf[11].z, a.z);  a.w = fmaf(m10, cf[11].w, a.w);
        a.x = fmaf(m11, cf[12].x, a.x);  a.y = fmaf(m11, cf[12].y, a.y);
        a.z = fmaf(m11, cf[12].z, a.z);  a.w = fmaf(m11, cf[12].w, a.w);
        a.x = fmaf(m12, cf[13].x, a.x);  a.y = fmaf(m12, cf[13].y, a.y);
        a.z = fmaf(m12, cf[13].z, a.z);  a.w = fmaf(m12, cf[13].w, a.w);

        stcs4(outp + (long)i * 16 * V, a);     // streaming store, coalesced
    }

    // ---- sigmas: acos applied at copy-out (off the scan critical path) ----
    const float4* sb4 = reinterpret_cast<const float4*>(sbuf);
    float* so = sigmas + (long)b * T;
    float4 s0 = sb4[t];
    float4 s1 = sb4[t + 256];
    s0.x = sig_from_w(s0.x); s0.y = sig_from_w(s0.y);
    s0.z = sig_from_w(s0.z); s0.w = sig_from_w(s0.w);
    s1.x = sig_from_w(s1.x); s1.y = sig_from_w(s1.y);
    s1.z = sig_from_w(s1.z); s1.w = sig_from_w(s1.w);
    stcs4(so + t * 4, s0);
    stcs4(so + 1024 + t * 4, s1);
}

// ---------------------------------------------------------------------------
extern "C" void kernel_launch(void* const* d_in, const int* in_sizes, int n_in,
                              void* d_out, int out_size) {
    const int*   tokens = (const int*)  d_in[0];
    const float* eW1    = (const float*)d_in[1];
    const float* eb1    = (const float*)d_in[2];
    const float* eW2    = (const float*)d_in[3];
    const float* eb2    = (const float*)d_in[4];
    const float* hW1    = (const float*)d_in[5];
    const float* hb1    = (const float*)d_in[6];
    const float* hW2    = (const float*)d_in[7];
    const float* hb2    = (const float*)d_in[8];

    float* out    = (float*)d_out;
    float* logits = out;                       // (B,T,V)
    float* sigmas = out + (long)B * T * V;     // (B,T)

    precompute_kernel<<<128, 64>>>(eW1, eb1, eW2, eb2, hW1, hb1, hW2, hb2);
    fused_kernel<<<B, 256>>>(tokens, logits, sigmas);
}